// round 15
// baseline (speedup 1.0000x reference)
#include <cuda_runtime.h>
#include <cuda_bf16.h>
#include <cuda_fp16.h>
#include <cstdint>

// ============================================================================
// out[64,8] = exp(-1e-4 * ||x_b - c_j||^2) @ fc_w.T + fc_b
//   x: [64, 65536] f32, centers: [500, 65536] f32
// K1 (round-10 best, 52.8us): split-K x split-M, grid 512, 256 thr, 48KB,
//     occ 4, one wave. bf16 mma.sync, f32 acc, k-split + smem exchange.
//     f16 partials [c][s=256][b].
// K0: finalize norms once -> cs[512], xs[64]; block 0 zeroes g_acc.
// K2: partial reduction + rbf + FUSED fc via int64 fixed-point atomics
//     (deterministic: integer adds are associative). No g_rbf round trip.
// K3: tiny finalize (1 block): g_acc -> out.
// Base sm_100 only (harness compiles compute_100: no tcgen05).
// ============================================================================

#define GAMMA_F 1e-4f
#define FXP_SCALE 281474976710656.0            // 2^48
#define FXP_INV   (1.0 / 281474976710656.0)

static constexpr int S_SPLIT = 256;   // K chunks
static constexpr int KC      = 256;   // K per chunk
static constexpr int NB      = 64;    // batch
static constexpr int NCPAD   = 512;
static constexpr int NSB     = 8;     // 32-row center sub-blocks per CTA

// -------- scratch --------
__device__ __half g_parth[(size_t)NCPAD * S_SPLIT * NB];  // [c][s][b] 16 MB f16
__device__ float  g_csq_p[(size_t)NCPAD * S_SPLIT];
__device__ float  g_xsq_p[(size_t)NB    * S_SPLIT];       // [b][s]
__device__ float  g_cs   [NCPAD];
__device__ float  g_xs   [NB];
__device__ unsigned long long g_acc[NB * 8];              // fixed-point out acc

// -------- helpers --------
__device__ __forceinline__ uint32_t smem_u32(const void* p) {
    uint32_t a;
    asm("{ .reg .u64 t; cvta.to.shared.u64 t, %1; cvt.u32.u64 %0, t; }" : "=r"(a) : "l"(p));
    return a;
}
// 64-row tile (x): atoms 8 rows x 64 bf16; 8 atom-rows per 64-k block
__device__ __forceinline__ uint32_t roff64(int row, int k) {
    uint32_t r7 = (uint32_t)(row & 7);
    return (((uint32_t)(k >> 6) * 8u + (uint32_t)(row >> 3)) << 10)
         + r7 * 128u + (((uint32_t)(k & 63) * 2u) ^ (r7 << 4));
}
// 32-row tile (c): 4 atom-rows per 64-k block
__device__ __forceinline__ uint32_t roff32(int row, int k) {
    uint32_t r7 = (uint32_t)(row & 7);
    return (((uint32_t)(k >> 6) * 4u + (uint32_t)(row >> 3)) << 10)
         + r7 * 128u + (((uint32_t)(k & 63) * 2u) ^ (r7 << 4));
}
__device__ __forceinline__ uint32_t pack_bf16x2(float a, float b) {
    __nv_bfloat162 t = __floats2bfloat162_rn(a, b);
    return *reinterpret_cast<uint32_t*>(&t);
}
__device__ __forceinline__ void ldsm_x4(uint32_t* r, uint32_t addr) {
    asm volatile("ldmatrix.sync.aligned.m8n8.x4.shared.b16 {%0,%1,%2,%3}, [%4];"
                 : "=r"(r[0]), "=r"(r[1]), "=r"(r[2]), "=r"(r[3]) : "r"(addr));
}
__device__ __forceinline__ void mma_bf16(float* d, const uint32_t* a, const uint32_t* b) {
    asm volatile("mma.sync.aligned.m16n8k16.row.col.f32.bf16.bf16.f32 "
                 "{%0,%1,%2,%3}, {%4,%5,%6,%7}, {%8,%9}, {%0,%1,%2,%3};"
                 : "+f"(d[0]), "+f"(d[1]), "+f"(d[2]), "+f"(d[3])
                 : "r"(a[0]), "r"(a[1]), "r"(a[2]), "r"(a[3]), "r"(b[0]), "r"(b[1]));
}
__device__ __forceinline__ float dot4(float4 v) {
    return v.x * v.x + v.y * v.y + v.z * v.z + v.w * v.w;
}
__device__ __forceinline__ float warp_sum(float v) {
    #pragma unroll
    for (int d = 16; d > 0; d >>= 1) v += __shfl_xor_sync(0xffffffffu, v, d);
    return v;
}

// -------- SMEM: x 32KB | c 16KB (MMA-idle: acc-exchange scratch 8KB) --------
static constexpr int SMEM_X     = 0;
static constexpr int SMEM_C     = 32768;
static constexpr int SMEM_TOTAL = 49152;

// ============================================================================
// Kernel 1  (round-10 best, verbatim)
// ============================================================================
__global__ void __launch_bounds__(256, 4)
svm_main_kernel(const float* __restrict__ x, const float* __restrict__ centers) {
    extern __shared__ char smem[];
    const uint32_t smem_base = smem_u32(smem);
    const int tid = threadIdx.x;
    const int wid = tid >> 5;
    const int lid = tid & 31;
    const int s   = blockIdx.x >> 1;       // k-chunk
    const int mh  = blockIdx.x & 1;        // m-half (center rows mh*256..)
    const size_t k0 = (size_t)s * KC;

    const int kA = 4 * lid, kB = 128 + 4 * lid;

    // ---- prologue: convert x chunk; warp w -> rows 8w..8w+7, coalesced ----
    {
        char* tile = smem + SMEM_X;
        #pragma unroll
        for (int q = 0; q < 8; q += 2) {
            const int r0 = wid * 8 + q, r1 = r0 + 1;
            const float4* g0 = reinterpret_cast<const float4*>(x + (size_t)r0 * 65536 + k0);
            const float4* g1 = reinterpret_cast<const float4*>(x + (size_t)r1 * 65536 + k0);
            float4 a0 = g0[lid], b0 = g0[lid + 32];
            float4 a1 = g1[lid], b1 = g1[lid + 32];
            *reinterpret_cast<uint2*>(tile + roff64(r0, kA)) =
                make_uint2(pack_bf16x2(a0.x, a0.y), pack_bf16x2(a0.z, a0.w));
            *reinterpret_cast<uint2*>(tile + roff64(r0, kB)) =
                make_uint2(pack_bf16x2(b0.x, b0.y), pack_bf16x2(b0.z, b0.w));
            *reinterpret_cast<uint2*>(tile + roff64(r1, kA)) =
                make_uint2(pack_bf16x2(a1.x, a1.y), pack_bf16x2(a1.z, a1.w));
            *reinterpret_cast<uint2*>(tile + roff64(r1, kB)) =
                make_uint2(pack_bf16x2(b1.x, b1.y), pack_bf16x2(b1.z, b1.w));
            float s0 = warp_sum(dot4(a0) + dot4(b0));
            float s1 = warp_sum(dot4(a1) + dot4(b1));
            if (mh == 0 && lid == 0) {
                g_xsq_p[(size_t)r0 * S_SPLIT + s] = s0;
                g_xsq_p[(size_t)r1 * S_SPLIT + s] = s1;
            }
        }
    }

    const int khalf = wid >> 2;            // 0: k 0..127, 1: k 128..255
    const int j4    = wid & 3;
    const int nbase = j4 * 16;
    const int kbase = khalf * 128;
    const int sel = lid >> 3;
    const int l7  = lid & 7;
    const int a_row = l7 + (sel & 1) * 8;
    const int a_kd  = (sel >> 1) * 8;
    const int b_row = nbase + l7 + (sel >> 1) * 8;
    const int b_kd  = (sel & 1) * 8;
    const uint32_t xb = smem_base + SMEM_X;
    const uint32_t cb = smem_base + SMEM_C;
    float* scratch = reinterpret_cast<float*>(smem + SMEM_C);   // overlaid

    for (int sb = 0; sb < NSB; sb++) {
        __syncthreads();   // prev MMA + scratch reads done -> c region free

        // ---- convert center sub-block (32 rows; warp w -> rows 4w..4w+3) ----
        {
            char* tile = smem + SMEM_C;
            const int gbase = mh * 256 + sb * 32;
            #pragma unroll
            for (int q = 0; q < 4; q += 2) {
                const int r0 = wid * 4 + q, r1 = r0 + 1;
                const int gr0 = gbase + r0, gr1 = gbase + r1;
                const float4 z = make_float4(0.f, 0.f, 0.f, 0.f);
                float4 a0, b0, a1, b1;
                if (gr0 < 500) {
                    const float4* g0 =
                        reinterpret_cast<const float4*>(centers + (size_t)gr0 * 65536 + k0);
                    a0 = g0[lid]; b0 = g0[lid + 32];
                } else { a0 = z; b0 = z; }
                if (gr1 < 500) {
                    const float4* g1 =
                        reinterpret_cast<const float4*>(centers + (size_t)gr1 * 65536 + k0);
                    a1 = g1[lid]; b1 = g1[lid + 32];
                } else { a1 = z; b1 = z; }
                *reinterpret_cast<uint2*>(tile + roff32(r0, kA)) =
                    make_uint2(pack_bf16x2(a0.x, a0.y), pack_bf16x2(a0.z, a0.w));
                *reinterpret_cast<uint2*>(tile + roff32(r0, kB)) =
                    make_uint2(pack_bf16x2(b0.x, b0.y), pack_bf16x2(b0.z, b0.w));
                *reinterpret_cast<uint2*>(tile + roff32(r1, kA)) =
                    make_uint2(pack_bf16x2(a1.x, a1.y), pack_bf16x2(a1.z, a1.w));
                *reinterpret_cast<uint2*>(tile + roff32(r1, kB)) =
                    make_uint2(pack_bf16x2(b1.x, b1.y), pack_bf16x2(b1.z, b1.w));
                float s0 = warp_sum(dot4(a0) + dot4(b0));
                float s1 = warp_sum(dot4(a1) + dot4(b1));
                if (lid == 0) {
                    if (gr0 < 500) g_csq_p[(size_t)gr0 * S_SPLIT + s] = s0;
                    if (gr1 < 500) g_csq_p[(size_t)gr1 * S_SPLIT + s] = s1;
                }
            }
        }
        __syncthreads();

        // ---- MMA: warp tile m32 x n16 over its 128-k half ----
        float acc[16];
        #pragma unroll
        for (int i = 0; i < 16; i++) acc[i] = 0.f;

        #pragma unroll 8
        for (int kk = 0; kk < 128; kk += 16) {
            uint32_t af0[4], af1[4], bf[4];
            ldsm_x4(af0, cb + roff32(a_row,      kbase + kk + a_kd));
            ldsm_x4(af1, cb + roff32(16 + a_row, kbase + kk + a_kd));
            ldsm_x4(bf,  xb + roff64(b_row,      kbase + kk + b_kd));
            mma_bf16(acc + 0,  af0, bf);
            mma_bf16(acc + 4,  af0, bf + 2);
            mma_bf16(acc + 8,  af1, bf);
            mma_bf16(acc + 12, af1, bf + 2);
        }
        __syncthreads();   // all ldsm reads of c tile done -> scratch writable

        // ---- k-half exchange: warps 4-7 publish, warps 0-3 combine+store ----
        if (khalf == 1) {
            float4* dst = reinterpret_cast<float4*>(scratch) + (j4 * 32 + lid) * 4;
            dst[0] = make_float4(acc[0],  acc[1],  acc[2],  acc[3]);
            dst[1] = make_float4(acc[4],  acc[5],  acc[6],  acc[7]);
            dst[2] = make_float4(acc[8],  acc[9],  acc[10], acc[11]);
            dst[3] = make_float4(acc[12], acc[13], acc[14], acc[15]);
        }
        __syncthreads();
        if (khalf == 0) {
            const float4* src = reinterpret_cast<const float4*>(scratch) + (j4 * 32 + lid) * 4;
            #pragma unroll
            for (int i4 = 0; i4 < 4; i4++) {
                float4 v = src[i4];
                acc[4 * i4 + 0] += v.x; acc[4 * i4 + 1] += v.y;
                acc[4 * i4 + 2] += v.z; acc[4 * i4 + 3] += v.w;
            }
            const int r0 = mh * 256 + sb * 32 + (lid >> 2);
            const int c0 = nbase + (lid & 3) * 2;
            #pragma unroll
            for (int mi = 0; mi < 2; mi++) {
                #pragma unroll
                for (int ni = 0; ni < 2; ni++) {
                    const int col = c0 + 8 * ni;
                    const float* a4 = acc + mi * 8 + ni * 4;
                    __half* p0 = g_parth + (((size_t)(r0 + 16 * mi)     * S_SPLIT + s) << 6) + col;
                    __half* p1 = g_parth + (((size_t)(r0 + 16 * mi + 8) * S_SPLIT + s) << 6) + col;
                    *reinterpret_cast<__half2*>(p0) = __floats2half2_rn(a4[0], a4[1]);
                    *reinterpret_cast<__half2*>(p1) = __floats2half2_rn(a4[2], a4[3]);
                }
            }
        }
    }
}

// ============================================================================
// Kernel 0: finalize norms once (576 warp-rows); block 0 zeroes g_acc
// ============================================================================
__global__ void __launch_bounds__(256)
svm_norm_kernel() {
    if (blockIdx.x == 0) {
        g_acc[threadIdx.x * 2]     = 0ull;
        g_acc[threadIdx.x * 2 + 1] = 0ull;
    }
    const int row  = blockIdx.x * 8 + (threadIdx.x >> 5);   // grid 72 -> 576
    const int lane = threadIdx.x & 31;
    const float* src = (row < NCPAD) ? (g_csq_p + (size_t)row * S_SPLIT)
                                     : (g_xsq_p + (size_t)(row - NCPAD) * S_SPLIT);
    const float4* s4 = reinterpret_cast<const float4*>(src);
    float4 a = s4[lane], b = s4[lane + 32];
    float v = warp_sum(a.x + a.y + a.z + a.w + b.x + b.y + b.z + b.w);
    if (lane == 0) {
        if (row < NCPAD) { if (row < 500) g_cs[row] = v; }
        else             g_xs[row - NCPAD] = v;
    }
}

// ============================================================================
// Kernel 2: partial reduction + rbf + FUSED fc (fixed-point atomics)
// ============================================================================
__global__ void __launch_bounds__(512)
svm_rbf_kernel(const float* __restrict__ fc_w) {
    __shared__ float red[16][NB];
    __shared__ float srbf[NB];
    __shared__ float swc[8];
    const int c   = blockIdx.x;          // 0..499
    const int tid = threadIdx.x;         // 512
    const int sp   = tid >> 5;           // 0..15 (16 s-values each)
    const int lane = tid & 31;

    // cross partials: coalesced half2 stream
    {
        const __half2* p =
            reinterpret_cast<const __half2*>(g_parth + ((size_t)c * S_SPLIT + sp * 16) * NB) + lane;
        float2 a = make_float2(0.f, 0.f);
        #pragma unroll
        for (int i = 0; i < 16; i++) {
            float2 f = __half22float2(p[(size_t)i * 32]);
            a.x += f.x; a.y += f.y;
        }
        red[sp][2 * lane]     = a.x;
        red[sp][2 * lane + 1] = a.y;
    }
    if (tid < 8) swc[tid] = fc_w[tid * 500 + c];
    __syncthreads();
    if (tid < NB) {
        float cross = 0.f;
        #pragma unroll
        for (int i = 0; i < 16; i++) cross += red[i][tid];
        float dist = g_xs[tid] - 2.0f * cross + g_cs[c];
        srbf[tid] = expf(-GAMMA_F * dist);
    }
    __syncthreads();

    // fused fc: thread (i = tid>>6, b = tid&63)
    {
        const int b = tid & 63;
        const int i = tid >> 6;
        double v = (double)srbf[b] * (double)swc[i] * FXP_SCALE;
        long long q = __double2ll_rn(v);
        atomicAdd(&g_acc[b * 8 + i], (unsigned long long)q);
    }
}

// ============================================================================
// Kernel 3: tiny finalize: g_acc -> out  (1 block, 512 threads)
// ============================================================================
__global__ void __launch_bounds__(512)
svm_out_kernel(const float* __restrict__ fc_b, float* __restrict__ out) {
    const int t = threadIdx.x;           // t = b*8 + i
    long long q = (long long)g_acc[t];
    out[t] = (float)((double)q * FXP_INV + (double)fc_b[t & 7]);
}

// ============================================================================
extern "C" void kernel_launch(void* const* d_in, const int* in_sizes, int n_in,
                              void* d_out, int out_size) {
    const float* x       = (const float*)d_in[0];
    const float* centers = (const float*)d_in[1];
    const float* fc_w    = (const float*)d_in[2];
    const float* fc_b    = (const float*)d_in[3];
    float* out = (float*)d_out;

    cudaFuncSetAttribute(svm_main_kernel, cudaFuncAttributeMaxDynamicSharedMemorySize, SMEM_TOTAL);

    svm_main_kernel<<<2 * S_SPLIT, 256, SMEM_TOTAL>>>(x, centers);
    svm_norm_kernel<<<72, 256>>>();
    svm_rbf_kernel<<<500, 512>>>(fc_w);
    svm_out_kernel<<<1, 512>>>(fc_b, out);
}

// round 16
// speedup vs baseline: 1.2490x; 1.2490x over previous
#include <cuda_runtime.h>
#include <cuda_bf16.h>
#include <cuda_fp16.h>
#include <cstdint>

// ============================================================================
// out[64,8] = exp(-1e-4 * ||x_b - c_j||^2) @ fc_w.T + fc_b
//   x: [64, 65536] f32, centers: [500, 65536] f32
// K1 (round-10 best, 52.8us): split-K x split-M, grid 512, 256 thr, 48KB,
//     occ 4, one wave. bf16 mma.sync, f32 acc, k-split + smem exchange.
//     f16 partials [c][s=256][b].
// K0: finalize norms once -> cs[512], xs[64]; zero padded g_acc + counter.
// K2: partial reduction + rbf + fused fc via PADDED (128B/line) int64
//     fixed-point atomics (deterministic), + last-block writes out directly
//     (fence+counter). 3 launches total.
// Base sm_100 only (harness compiles compute_100: no tcgen05).
// ============================================================================

#define GAMMA_F 1e-4f
#define FXP_SCALE_F 281474976710656.0f         // 2^48 (exact in f32)
#define FXP_INV     (1.0 / 281474976710656.0)

static constexpr int S_SPLIT = 256;   // K chunks
static constexpr int KC      = 256;   // K per chunk
static constexpr int NB      = 64;    // batch
static constexpr int NCPAD   = 512;
static constexpr int NSB     = 8;     // 32-row center sub-blocks per CTA
static constexpr int ACC_PAD = 16;    // u64 stride -> 128B per counter

// -------- scratch --------
__device__ __half g_parth[(size_t)NCPAD * S_SPLIT * NB];  // [c][s][b] 16 MB f16
__device__ float  g_csq_p[(size_t)NCPAD * S_SPLIT];
__device__ float  g_xsq_p[(size_t)NB    * S_SPLIT];       // [b][s]
__device__ float  g_cs   [NCPAD];
__device__ float  g_xs   [NB];
__device__ unsigned long long g_acc[NB * 8 * ACC_PAD];    // padded fixed-point
__device__ unsigned int g_count;

// -------- helpers --------
__device__ __forceinline__ uint32_t smem_u32(const void* p) {
    uint32_t a;
    asm("{ .reg .u64 t; cvta.to.shared.u64 t, %1; cvt.u32.u64 %0, t; }" : "=r"(a) : "l"(p));
    return a;
}
// 64-row tile (x): atoms 8 rows x 64 bf16; 8 atom-rows per 64-k block
__device__ __forceinline__ uint32_t roff64(int row, int k) {
    uint32_t r7 = (uint32_t)(row & 7);
    return (((uint32_t)(k >> 6) * 8u + (uint32_t)(row >> 3)) << 10)
         + r7 * 128u + (((uint32_t)(k & 63) * 2u) ^ (r7 << 4));
}
// 32-row tile (c): 4 atom-rows per 64-k block
__device__ __forceinline__ uint32_t roff32(int row, int k) {
    uint32_t r7 = (uint32_t)(row & 7);
    return (((uint32_t)(k >> 6) * 4u + (uint32_t)(row >> 3)) << 10)
         + r7 * 128u + (((uint32_t)(k & 63) * 2u) ^ (r7 << 4));
}
__device__ __forceinline__ uint32_t pack_bf16x2(float a, float b) {
    __nv_bfloat162 t = __floats2bfloat162_rn(a, b);
    return *reinterpret_cast<uint32_t*>(&t);
}
__device__ __forceinline__ void ldsm_x4(uint32_t* r, uint32_t addr) {
    asm volatile("ldmatrix.sync.aligned.m8n8.x4.shared.b16 {%0,%1,%2,%3}, [%4];"
                 : "=r"(r[0]), "=r"(r[1]), "=r"(r[2]), "=r"(r[3]) : "r"(addr));
}
__device__ __forceinline__ void mma_bf16(float* d, const uint32_t* a, const uint32_t* b) {
    asm volatile("mma.sync.aligned.m16n8k16.row.col.f32.bf16.bf16.f32 "
                 "{%0,%1,%2,%3}, {%4,%5,%6,%7}, {%8,%9}, {%0,%1,%2,%3};"
                 : "+f"(d[0]), "+f"(d[1]), "+f"(d[2]), "+f"(d[3])
                 : "r"(a[0]), "r"(a[1]), "r"(a[2]), "r"(a[3]), "r"(b[0]), "r"(b[1]));
}
__device__ __forceinline__ float dot4(float4 v) {
    return v.x * v.x + v.y * v.y + v.z * v.z + v.w * v.w;
}
__device__ __forceinline__ float warp_sum(float v) {
    #pragma unroll
    for (int d = 16; d > 0; d >>= 1) v += __shfl_xor_sync(0xffffffffu, v, d);
    return v;
}

// -------- SMEM: x 32KB | c 16KB (MMA-idle: acc-exchange scratch 8KB) --------
static constexpr int SMEM_X     = 0;
static constexpr int SMEM_C     = 32768;
static constexpr int SMEM_TOTAL = 49152;

// ============================================================================
// Kernel 1  (round-10 best, verbatim)
// ============================================================================
__global__ void __launch_bounds__(256, 4)
svm_main_kernel(const float* __restrict__ x, const float* __restrict__ centers) {
    extern __shared__ char smem[];
    const uint32_t smem_base = smem_u32(smem);
    const int tid = threadIdx.x;
    const int wid = tid >> 5;
    const int lid = tid & 31;
    const int s   = blockIdx.x >> 1;       // k-chunk
    const int mh  = blockIdx.x & 1;        // m-half (center rows mh*256..)
    const size_t k0 = (size_t)s * KC;

    const int kA = 4 * lid, kB = 128 + 4 * lid;

    // ---- prologue: convert x chunk; warp w -> rows 8w..8w+7, coalesced ----
    {
        char* tile = smem + SMEM_X;
        #pragma unroll
        for (int q = 0; q < 8; q += 2) {
            const int r0 = wid * 8 + q, r1 = r0 + 1;
            const float4* g0 = reinterpret_cast<const float4*>(x + (size_t)r0 * 65536 + k0);
            const float4* g1 = reinterpret_cast<const float4*>(x + (size_t)r1 * 65536 + k0);
            float4 a0 = g0[lid], b0 = g0[lid + 32];
            float4 a1 = g1[lid], b1 = g1[lid + 32];
            *reinterpret_cast<uint2*>(tile + roff64(r0, kA)) =
                make_uint2(pack_bf16x2(a0.x, a0.y), pack_bf16x2(a0.z, a0.w));
            *reinterpret_cast<uint2*>(tile + roff64(r0, kB)) =
                make_uint2(pack_bf16x2(b0.x, b0.y), pack_bf16x2(b0.z, b0.w));
            *reinterpret_cast<uint2*>(tile + roff64(r1, kA)) =
                make_uint2(pack_bf16x2(a1.x, a1.y), pack_bf16x2(a1.z, a1.w));
            *reinterpret_cast<uint2*>(tile + roff64(r1, kB)) =
                make_uint2(pack_bf16x2(b1.x, b1.y), pack_bf16x2(b1.z, b1.w));
            float s0 = warp_sum(dot4(a0) + dot4(b0));
            float s1 = warp_sum(dot4(a1) + dot4(b1));
            if (mh == 0 && lid == 0) {
                g_xsq_p[(size_t)r0 * S_SPLIT + s] = s0;
                g_xsq_p[(size_t)r1 * S_SPLIT + s] = s1;
            }
        }
    }

    const int khalf = wid >> 2;            // 0: k 0..127, 1: k 128..255
    const int j4    = wid & 3;
    const int nbase = j4 * 16;
    const int kbase = khalf * 128;
    const int sel = lid >> 3;
    const int l7  = lid & 7;
    const int a_row = l7 + (sel & 1) * 8;
    const int a_kd  = (sel >> 1) * 8;
    const int b_row = nbase + l7 + (sel >> 1) * 8;
    const int b_kd  = (sel & 1) * 8;
    const uint32_t xb = smem_base + SMEM_X;
    const uint32_t cb = smem_base + SMEM_C;
    float* scratch = reinterpret_cast<float*>(smem + SMEM_C);   // overlaid

    for (int sb = 0; sb < NSB; sb++) {
        __syncthreads();   // prev MMA + scratch reads done -> c region free

        // ---- convert center sub-block (32 rows; warp w -> rows 4w..4w+3) ----
        {
            char* tile = smem + SMEM_C;
            const int gbase = mh * 256 + sb * 32;
            #pragma unroll
            for (int q = 0; q < 4; q += 2) {
                const int r0 = wid * 4 + q, r1 = r0 + 1;
                const int gr0 = gbase + r0, gr1 = gbase + r1;
                const float4 z = make_float4(0.f, 0.f, 0.f, 0.f);
                float4 a0, b0, a1, b1;
                if (gr0 < 500) {
                    const float4* g0 =
                        reinterpret_cast<const float4*>(centers + (size_t)gr0 * 65536 + k0);
                    a0 = g0[lid]; b0 = g0[lid + 32];
                } else { a0 = z; b0 = z; }
                if (gr1 < 500) {
                    const float4* g1 =
                        reinterpret_cast<const float4*>(centers + (size_t)gr1 * 65536 + k0);
                    a1 = g1[lid]; b1 = g1[lid + 32];
                } else { a1 = z; b1 = z; }
                *reinterpret_cast<uint2*>(tile + roff32(r0, kA)) =
                    make_uint2(pack_bf16x2(a0.x, a0.y), pack_bf16x2(a0.z, a0.w));
                *reinterpret_cast<uint2*>(tile + roff32(r0, kB)) =
                    make_uint2(pack_bf16x2(b0.x, b0.y), pack_bf16x2(b0.z, b0.w));
                *reinterpret_cast<uint2*>(tile + roff32(r1, kA)) =
                    make_uint2(pack_bf16x2(a1.x, a1.y), pack_bf16x2(a1.z, a1.w));
                *reinterpret_cast<uint2*>(tile + roff32(r1, kB)) =
                    make_uint2(pack_bf16x2(b1.x, b1.y), pack_bf16x2(b1.z, b1.w));
                float s0 = warp_sum(dot4(a0) + dot4(b0));
                float s1 = warp_sum(dot4(a1) + dot4(b1));
                if (lid == 0) {
                    if (gr0 < 500) g_csq_p[(size_t)gr0 * S_SPLIT + s] = s0;
                    if (gr1 < 500) g_csq_p[(size_t)gr1 * S_SPLIT + s] = s1;
                }
            }
        }
        __syncthreads();

        // ---- MMA: warp tile m32 x n16 over its 128-k half ----
        float acc[16];
        #pragma unroll
        for (int i = 0; i < 16; i++) acc[i] = 0.f;

        #pragma unroll 8
        for (int kk = 0; kk < 128; kk += 16) {
            uint32_t af0[4], af1[4], bf[4];
            ldsm_x4(af0, cb + roff32(a_row,      kbase + kk + a_kd));
            ldsm_x4(af1, cb + roff32(16 + a_row, kbase + kk + a_kd));
            ldsm_x4(bf,  xb + roff64(b_row,      kbase + kk + b_kd));
            mma_bf16(acc + 0,  af0, bf);
            mma_bf16(acc + 4,  af0, bf + 2);
            mma_bf16(acc + 8,  af1, bf);
            mma_bf16(acc + 12, af1, bf + 2);
        }
        __syncthreads();   // all ldsm reads of c tile done -> scratch writable

        // ---- k-half exchange: warps 4-7 publish, warps 0-3 combine+store ----
        if (khalf == 1) {
            float4* dst = reinterpret_cast<float4*>(scratch) + (j4 * 32 + lid) * 4;
            dst[0] = make_float4(acc[0],  acc[1],  acc[2],  acc[3]);
            dst[1] = make_float4(acc[4],  acc[5],  acc[6],  acc[7]);
            dst[2] = make_float4(acc[8],  acc[9],  acc[10], acc[11]);
            dst[3] = make_float4(acc[12], acc[13], acc[14], acc[15]);
        }
        __syncthreads();
        if (khalf == 0) {
            const float4* src = reinterpret_cast<const float4*>(scratch) + (j4 * 32 + lid) * 4;
            #pragma unroll
            for (int i4 = 0; i4 < 4; i4++) {
                float4 v = src[i4];
                acc[4 * i4 + 0] += v.x; acc[4 * i4 + 1] += v.y;
                acc[4 * i4 + 2] += v.z; acc[4 * i4 + 3] += v.w;
            }
            const int r0 = mh * 256 + sb * 32 + (lid >> 2);
            const int c0 = nbase + (lid & 3) * 2;
            #pragma unroll
            for (int mi = 0; mi < 2; mi++) {
                #pragma unroll
                for (int ni = 0; ni < 2; ni++) {
                    const int col = c0 + 8 * ni;
                    const float* a4 = acc + mi * 8 + ni * 4;
                    __half* p0 = g_parth + (((size_t)(r0 + 16 * mi)     * S_SPLIT + s) << 6) + col;
                    __half* p1 = g_parth + (((size_t)(r0 + 16 * mi + 8) * S_SPLIT + s) << 6) + col;
                    *reinterpret_cast<__half2*>(p0) = __floats2half2_rn(a4[0], a4[1]);
                    *reinterpret_cast<__half2*>(p1) = __floats2half2_rn(a4[2], a4[3]);
                }
            }
        }
    }
}

// ============================================================================
// Kernel 0: finalize norms once (576 warp-rows); zero padded g_acc + counter
// ============================================================================
__global__ void __launch_bounds__(256)
svm_norm_kernel() {
    const int gid = blockIdx.x * 256 + threadIdx.x;
    if (gid < NB * 8 * ACC_PAD) g_acc[gid] = 0ull;     // 8192 slots < 72*256
    if (gid == 0) g_count = 0u;

    const int row  = blockIdx.x * 8 + (threadIdx.x >> 5);   // grid 72 -> 576
    const int lane = threadIdx.x & 31;
    const float* src = (row < NCPAD) ? (g_csq_p + (size_t)row * S_SPLIT)
                                     : (g_xsq_p + (size_t)(row - NCPAD) * S_SPLIT);
    const float4* s4 = reinterpret_cast<const float4*>(src);
    float4 a = s4[lane], b = s4[lane + 32];
    float v = warp_sum(a.x + a.y + a.z + a.w + b.x + b.y + b.z + b.w);
    if (lane == 0) {
        if (row < NCPAD) { if (row < 500) g_cs[row] = v; }
        else             g_xs[row - NCPAD] = v;
    }
}

// ============================================================================
// Kernel 2: reduction + rbf + fused fc (padded atomics) + last-block output
// ============================================================================
__global__ void __launch_bounds__(512)
svm_rbf_kernel(const float* __restrict__ fc_w,
               const float* __restrict__ fc_b,
               float* __restrict__ out) {
    __shared__ float red[16][NB];
    __shared__ float srbf[NB];
    __shared__ float swc[8];
    __shared__ unsigned int s_rank;
    const int c   = blockIdx.x;          // 0..499
    const int tid = threadIdx.x;         // 512
    const int sp   = tid >> 5;           // 0..15 (16 s-values each)
    const int lane = tid & 31;

    // cross partials: coalesced half2 stream
    {
        const __half2* p =
            reinterpret_cast<const __half2*>(g_parth + ((size_t)c * S_SPLIT + sp * 16) * NB) + lane;
        float2 a = make_float2(0.f, 0.f);
        #pragma unroll
        for (int i = 0; i < 16; i++) {
            float2 f = __half22float2(p[(size_t)i * 32]);
            a.x += f.x; a.y += f.y;
        }
        red[sp][2 * lane]     = a.x;
        red[sp][2 * lane + 1] = a.y;
    }
    if (tid < 8) swc[tid] = fc_w[tid * 500 + c];
    __syncthreads();
    if (tid < NB) {
        float cross = 0.f;
        #pragma unroll
        for (int i = 0; i < 16; i++) cross += red[i][tid];
        float dist = g_xs[tid] - 2.0f * cross + g_cs[c];
        srbf[tid] = expf(-GAMMA_F * dist);
    }
    __syncthreads();

    // fused fc: thread (b = tid&63, i = tid>>6); one padded counter per (b,i)
    {
        const int b = tid & 63;
        const int i = tid >> 6;
        float v = srbf[b] * swc[i] * FXP_SCALE_F;
        long long q = __float2ll_rn(v);
        atomicAdd(&g_acc[(b * 8 + i) * ACC_PAD], (unsigned long long)q);
    }

    // last block finalizes (deterministic: int sums are order-independent)
    __threadfence();
    __syncthreads();
    if (tid == 0) s_rank = atomicAdd(&g_count, 1u);
    __syncthreads();
    if (s_rank == 499) {
        long long q = (long long)g_acc[tid * ACC_PAD];
        out[tid] = (float)((double)q * FXP_INV + (double)fc_b[tid & 7]);
    }
}

// ============================================================================
extern "C" void kernel_launch(void* const* d_in, const int* in_sizes, int n_in,
                              void* d_out, int out_size) {
    const float* x       = (const float*)d_in[0];
    const float* centers = (const float*)d_in[1];
    const float* fc_w    = (const float*)d_in[2];
    const float* fc_b    = (const float*)d_in[3];
    float* out = (float*)d_out;

    cudaFuncSetAttribute(svm_main_kernel, cudaFuncAttributeMaxDynamicSharedMemorySize, SMEM_TOTAL);

    svm_main_kernel<<<2 * S_SPLIT, 256, SMEM_TOTAL>>>(x, centers);
    svm_norm_kernel<<<72, 256>>>();
    svm_rbf_kernel<<<500, 512>>>(fc_w, fc_b, out);
}